// round 4
// baseline (speedup 1.0000x reference)
#include <cuda_runtime.h>
#include <cstddef>

#define NN 64
#define G  8            // batches per block
#define TB 128          // 16 threads per batch

// shared layout (float offsets)
#define SA2_OFF 0                         // [32 e][64 n]               2048
#define SB3_OFF 2048                      // [64 n][68]                 4352
#define SX_OFF  (SB3_OFF + 4352)          // [8 g][65 float2]           1040
#define SM_OFF  (SX_OFF + 1040)           // [8 g][1040] skewed M rows  8320
#define SS_OFF  (SM_OFF + 8320)           // [8 g][16 t][17] S          2176
#define SST_OFF (SS_OFF + 2176)           // [8 g][16 t][17] S^T        2176
#define SQT_OFF (SST_OFF + 2176)          // [8 g][16 slots][4]          512
#define SVL_OFF (SQT_OFF + 512)           // [64 n][33]                 2112
#define SVR_OFF (SVL_OFF + 2112)          // [64 n][33]                 2112
#define SMEM_FLOATS (SVR_OFF + 2112)      // 24848 floats = 99392 B

__device__ __forceinline__ float nan0(float h) {
    unsigned u = __float_as_uint(h);
    return ((u & 0x7fffffffu) > 0x7f800000u) ? 0.0f : h;
}

__global__ __launch_bounds__(TB, 2)
void tdvp_kernel(const float* __restrict__ xg, const float* __restrict__ Ag,
                 const float* __restrict__ Bg, const float* __restrict__ sg,
                 float* __restrict__ yg)
{
    extern __shared__ float sm[];
    float*  sA2 = sm + SA2_OFF;
    float*  sB3 = sm + SB3_OFF;
    float2* sx  = (float2*)(sm + SX_OFF);
    float*  sM  = sm + SM_OFF;
    float*  sS  = sm + SS_OFF;
    float*  sST = sm + SST_OFF;
    float*  sQT = sm + SQT_OFF;
    float*  svL = sm + SVL_OFF;
    float*  svR = sm + SVR_OFF;

    const int tid = threadIdx.x;
    const int b0  = blockIdx.x * G;

    // ---------------- stage 0: load inputs ----------------
    for (int i = tid; i < NN * 32; i += TB) {           // sA2[e*64+n] = A[n*32+e]
        int n = i & 63, e = i >> 6;
        sA2[i] = Ag[n * 32 + e];
    }
    for (int i = tid; i < NN * 64; i += TB) {           // sB3[n*68 + rem]
        int n = i >> 6, rem = i & 63;
        sB3[n * 68 + rem] = Bg[i];
    }
    const float2* xv = (const float2*)xg;
    for (int idx = tid; idx < G * NN; idx += TB) {
        float2 v = xv[(size_t)b0 * NN + idx];
        float inv = rsqrtf(v.x * v.x + v.y * v.y);
        v.x *= inv; v.y *= inv;
        sx[(idx >> 6) * 65 + (idx & 63)] = v;
    }
    __syncthreads();

    const int g    = tid >> 4;
    const int t_in = tid & 15;

    // ---------------- stage 1: build M once, segment products S_t ----------------
    {
        float P[16], Mk[16];
        float* mbase = sM + g * 1040;

        #pragma unroll
        for (int k = 0; k < 4; ++k) {
            const int n = 4 * t_in + k;
            float2 xn = sx[g * 65 + n];
            float* dst = (k == 0) ? P : Mk;
            #pragma unroll
            for (int e = 0; e < 16; ++e)
                dst[e] = fmaf(sA2[(2 * e) * 64 + n], xn.x, sA2[(2 * e + 1) * 64 + n] * xn.y);
            // store M[n] as 4 row-float4s, chunk q at slot (q + (n>>3)) & 3
            float* mb = mbase + n * 16;
            const int rot = (n >> 3) & 3;
            #pragma unroll
            for (int q = 0; q < 4; ++q)
                ((float4*)mb)[(q + rot) & 3] =
                    make_float4(dst[4*q], dst[4*q+1], dst[4*q+2], dst[4*q+3]);
            if (k > 0) {
                float Pn[16];
                #pragma unroll
                for (int i = 0; i < 4; ++i)
                    #pragma unroll
                    for (int c = 0; c < 4; ++c)
                        Pn[i*4+c] = P[i*4+0]*Mk[0*4+c] + P[i*4+1]*Mk[1*4+c]
                                  + P[i*4+2]*Mk[2*4+c] + P[i*4+3]*Mk[3*4+c];
                #pragma unroll
                for (int e = 0; e < 16; ++e) P[e] = Pn[e];
            }
        }
        float* ss  = sS  + g * 272 + t_in * 17;
        float* sst = sST + g * 272 + t_in * 17;
        #pragma unroll
        for (int e = 0; e < 16; ++e) {
            ss[e]  = P[e];
            sst[e] = P[(e & 3) * 4 + (e >> 2)];
        }
    }
    __syncthreads();

    // ---------------- stage 2: boundary vectors (unified fwd/bwd, 2 lanes/batch) ----------------
    if (t_in == 0 || t_in == 8) {
        const int dir = (t_in == 8);
        const float* matBase = dir ? (sS + g * 272) : (sST + g * 272);
        float* qt = sQT + g * 64 + (dir ? 32 : 0);
        // pre-store identity boundary: fwd q_0 (slot 0), bwd T_16 (slot 7)
        {
            const int s0 = dir ? 7 : 0;
            qt[s0*4+0] = 1.f; qt[s0*4+1] = 0.f; qt[s0*4+2] = 0.f; qt[s0*4+3] = 0.f;
        }
        float v0 = 1.f, v1 = 0.f, v2 = 0.f, v3 = 0.f;
        #pragma unroll 1
        for (int step = 0; step < 15; ++step) {
            const int h = dir ? (15 - step) : step;
            const float* Mt = matBase + h * 17;
            float t0 = Mt[0]*v0  + Mt[1]*v1  + Mt[2]*v2  + Mt[3]*v3;
            float t1 = Mt[4]*v0  + Mt[5]*v1  + Mt[6]*v2  + Mt[7]*v3;
            float t2 = Mt[8]*v0  + Mt[9]*v1  + Mt[10]*v2 + Mt[11]*v3;
            float t3 = Mt[12]*v0 + Mt[13]*v1 + Mt[14]*v2 + Mt[15]*v3;
            v0 = t0; v1 = t1; v2 = t2; v3 = t3;
            int slot; bool st;
            if (!dir) { st = (step & 1) != 0;              slot = (step + 1) >> 1; }
            else      { st = ((h & 1) == 0) && (h >= 2);   slot = (h - 2) >> 1;    }
            if (st) { qt[slot*4+0] = v0; qt[slot*4+1] = v1; qt[slot*4+2] = v2; qt[slot*4+3] = v3; }
        }
    }
    __syncthreads();

    // ---------------- stage 3: expand 8 positions per segment thread ----------------
    {
        const float* mbase = sM + g * 1040;
        if (t_in < 8) {
            const int s = t_in;
            const int rot = s & 3;
            float4 v = ((const float4*)(sQT + g * 64))[s];
            { float* d = svL + (8*s) * 33 + g * 4; d[0]=v.x; d[1]=v.y; d[2]=v.z; d[3]=v.w; }
            #pragma unroll
            for (int j = 0; j < 7; ++j) {
                const float* mb = mbase + (8*s + j) * 16;
                float4 R0 = ((const float4*)mb)[(0 + rot) & 3];
                float4 R1 = ((const float4*)mb)[(1 + rot) & 3];
                float4 R2 = ((const float4*)mb)[(2 + rot) & 3];
                float4 R3 = ((const float4*)mb)[(3 + rot) & 3];
                float4 nv;
                nv.x = v.x*R0.x + v.y*R1.x + v.z*R2.x + v.w*R3.x;
                nv.y = v.x*R0.y + v.y*R1.y + v.z*R2.y + v.w*R3.y;
                nv.z = v.x*R0.z + v.y*R1.z + v.z*R2.z + v.w*R3.z;
                nv.w = v.x*R0.w + v.y*R1.w + v.z*R2.w + v.w*R3.w;
                v = nv;
                float* d = svL + (8*s + j + 1) * 33 + g * 4;
                d[0]=v.x; d[1]=v.y; d[2]=v.z; d[3]=v.w;
            }
        } else {
            const int s = t_in - 8;
            const int rot = s & 3;
            float4 r = ((const float4*)(sQT + g * 64 + 32))[s];
            { float* d = svR + (8*s + 7) * 33 + g * 4; d[0]=r.x; d[1]=r.y; d[2]=r.z; d[3]=r.w; }
            #pragma unroll
            for (int k = 7; k >= 1; --k) {
                const float* mb = mbase + (8*s + k) * 16;
                float4 R0 = ((const float4*)mb)[(0 + rot) & 3];
                float4 R1 = ((const float4*)mb)[(1 + rot) & 3];
                float4 R2 = ((const float4*)mb)[(2 + rot) & 3];
                float4 R3 = ((const float4*)mb)[(3 + rot) & 3];
                float4 nr;
                nr.x = R0.x*r.x + R0.y*r.y + R0.z*r.z + R0.w*r.w;
                nr.y = R1.x*r.x + R1.y*r.y + R1.z*r.z + R1.w*r.w;
                nr.z = R2.x*r.x + R2.y*r.y + R2.z*r.z + R2.w*r.w;
                nr.w = R3.x*r.x + R3.y*r.y + R3.z*r.z + R3.w*r.w;
                r = nr;
                float* d = svR + (8*s + k - 1) * 33 + g * 4;
                d[0]=r.x; d[1]=r.y; d[2]=r.z; d[3]=r.w;
            }
        }
    }
    __syncthreads();

    // ---------------- output phase: thread owns 1 n x 4 batches ----------------
    {
        const int n  = tid & 63;
        const int bq = tid >> 6;           // 0..1
        const float s = sg[0];

        float u[4][4], a[4][4], H[4][4];
        #pragma unroll
        for (int b = 0; b < 4; ++b) {
            const int gb = bq * 4 + b;
            if (n == 0) { u[b][0]=1.f; u[b][1]=0.f; u[b][2]=0.f; u[b][3]=0.f; }
            else {
                const float* p = svL + n * 33 + gb * 4;
                float x0=p[0], x1=p[1], x2=p[2], x3=p[3];
                float nl = sqrtf(x0*x0 + x1*x1 + x2*x2 + x3*x3);
                float il = 1.0f / (nl + 1e-6f);
                u[b][0]=x0*il; u[b][1]=x1*il; u[b][2]=x2*il; u[b][3]=x3*il;
            }
            if (n == NN - 1) { a[b][0]=1.f; a[b][1]=0.f; a[b][2]=0.f; a[b][3]=0.f; }
            else {
                const float* p = svR + n * 33 + gb * 4;
                float x0=p[0], x1=p[1], x2=p[2], x3=p[3];
                float nr = sqrtf(x0*x0 + x1*x1 + x2*x2 + x3*x3);
                float ir = 1.0f / (nr + 1e-6f);
                a[b][0]=x0*ir; a[b][1]=x1*ir; a[b][2]=x2*ir; a[b][3]=x3*ir;
            }
            H[b][0]=0.f; H[b][1]=0.f; H[b][2]=0.f; H[b][3]=0.f;
        }

        #pragma unroll
        for (int c = 0; c < 16; ++c) {           // c = i*4 + l
            float4 bv = *(const float4*)(sB3 + n * 68 + c * 4);
            const int i = c >> 2, l = c & 3;
            #pragma unroll
            for (int b = 0; b < 4; ++b) {
                float w = u[b][i] * a[b][l];
                H[b][0] = fmaf(w, bv.x, H[b][0]);
                H[b][1] = fmaf(w, bv.y, H[b][1]);
                H[b][2] = fmaf(w, bv.z, H[b][2]);
                H[b][3] = fmaf(w, bv.w, H[b][3]);
            }
        }

        #pragma unroll
        for (int b = 0; b < 4; ++b) {
            const int gb = bq * 4 + b;
            float f = sqrtf(H[b][0]*H[b][0] + H[b][1]*H[b][1]
                          + H[b][2]*H[b][2] + H[b][3]*H[b][3]);
            float invf = s / (f + 1e-6f);
            float h00 = fmaxf(nan0(H[b][0] * invf), 0.f);
            float h01 = fmaxf(nan0(H[b][1] * invf), 0.f);
            float h10 = fmaxf(nan0(H[b][2] * invf), 0.f);
            float h11 = fmaxf(nan0(H[b][3] * invf), 0.f);
            float2 xn = sx[gb * 65 + n];
            float y0 = fmaf(h00, xn.x, h01 * xn.y);
            float y1 = fmaf(h10, xn.x, h11 * xn.y);
            sx[gb * 65 + n] = make_float2(y0, y1);
        }
    }
    __syncthreads();

    // ---------------- coalesced writeback ----------------
    float2* yv = (float2*)yg;
    for (int idx = tid; idx < G * NN; idx += TB)
        yv[(size_t)b0 * NN + idx] = sx[(idx >> 6) * 65 + (idx & 63)];
}

extern "C" void kernel_launch(void* const* d_in, const int* in_sizes, int n_in,
                              void* d_out, int out_size) {
    const float* x = (const float*)d_in[0];
    const float* A = (const float*)d_in[1];
    const float* B = (const float*)d_in[2];
    const float* s = (const float*)d_in[3];
    float* y = (float*)d_out;

    const int batch = in_sizes[0] / (NN * 2);
    const int grid  = batch / G;
    const size_t smem = (size_t)SMEM_FLOATS * sizeof(float);

    cudaFuncSetAttribute(tdvp_kernel, cudaFuncAttributeMaxDynamicSharedMemorySize, (int)smem);
    tdvp_kernel<<<grid, TB, smem>>>(x, A, B, s, y);
}

// round 5
// speedup vs baseline: 1.6591x; 1.6591x over previous
#include <cuda_runtime.h>
#include <cstddef>

#define NN 64
#define G  32          // batches per block
#define TB 128         // 4 threads per batch
#define BT 16384       // total batches (problem-fixed)

// L2-resident scratch: normalized prefix/suffix vectors, [n][b] coalesced
__device__ float4 gvL[NN * BT];
__device__ float4 gvR[NN * BT];

__device__ __forceinline__ float nan0(float h) {
    unsigned u = __float_as_uint(h);
    return ((u & 0x7fffffffu) > 0x7f800000u) ? 0.0f : h;
}

__global__ __launch_bounds__(TB, 4)
void tdvp_kernel(const float* __restrict__ xg, const float* __restrict__ Ag,
                 const float* __restrict__ Bg, const float* __restrict__ sg,
                 float* __restrict__ yg)
{
    __shared__ float  sA[NN * 32];        //  8 KB  A[n][32] original layout
    __shared__ float  sB[NN * 68];        // 17 KB  B[n] padded stride 68
    __shared__ float2 sx[G * 65];         // 16.6KB xn then y, [g][n] stride 65

    const int tid = threadIdx.x;
    const int b0  = blockIdx.x * G;

    // ---------------- stage inputs ----------------
    for (int i = tid; i < NN * 32; i += TB) sA[i] = Ag[i];
    for (int i = tid; i < NN * 64; i += TB) sB[(i >> 6) * 68 + (i & 63)] = Bg[i];
    const float2* xv = (const float2*)xg;
    for (int idx = tid; idx < G * NN; idx += TB) {
        float2 v = xv[(size_t)b0 * NN + idx];
        float inv = rsqrtf(v.x * v.x + v.y * v.y);
        v.x *= inv; v.y *= inv;
        sx[(idx >> 6) * 65 + (idx & 63)] = v;
    }
    __syncthreads();

    const int g = tid & 31;     // batch in block (lane index -> coalesced LDG)
    const int r = tid >> 5;     // role: warp0 fwd chain, warp1 bwd chain, 2-3 idle->output
    const int b = b0 + g;

    // build M[n] into m[16] (row-major l*4+r); sA reads are warp-broadcast
    #define BUILD_M(nn, m)                                                    \
    {                                                                         \
        float2 xn_ = sx[g * 65 + (nn)];                                       \
        const float4* ap_ = (const float4*)(sA + (nn) * 32);                  \
        _Pragma("unroll")                                                     \
        for (int q_ = 0; q_ < 8; ++q_) {                                      \
            float4 f_ = ap_[q_];                                              \
            m[2*q_]   = fmaf(f_.x, xn_.x, f_.y * xn_.y);                      \
            m[2*q_+1] = fmaf(f_.z, xn_.x, f_.w * xn_.y);                      \
        }                                                                     \
    }

    if (r == 0) {
        // forward: raw recurrence v <- v * M[n-1]; store normalized (off critical path)
        gvL[b] = make_float4(1.f, 0.f, 0.f, 0.f);
        float v0 = 1.f, v1 = 0.f, v2 = 0.f, v3 = 0.f;
        #pragma unroll 1
        for (int n = 1; n < NN; ++n) {
            float m[16];
            BUILD_M(n - 1, m);
            float t0 = v0*m[0] + v1*m[4] + v2*m[8]  + v3*m[12];
            float t1 = v0*m[1] + v1*m[5] + v2*m[9]  + v3*m[13];
            float t2 = v0*m[2] + v1*m[6] + v2*m[10] + v3*m[14];
            float t3 = v0*m[3] + v1*m[7] + v2*m[11] + v3*m[15];
            v0 = t0; v1 = t1; v2 = t2; v3 = t3;
            float d   = v0*v0 + v1*v1 + v2*v2 + v3*v3;
            float inv = 1.0f / (sqrtf(d) + 1e-6f);
            gvL[n * BT + b] = make_float4(v0*inv, v1*inv, v2*inv, v3*inv);
        }
    } else if (r == 1) {
        // backward: raw recurrence w <- M[n+1] * w
        gvR[(NN - 1) * BT + b] = make_float4(1.f, 0.f, 0.f, 0.f);
        float w0 = 1.f, w1 = 0.f, w2 = 0.f, w3 = 0.f;
        #pragma unroll 1
        for (int n = NN - 2; n >= 0; --n) {
            float m[16];
            BUILD_M(n + 1, m);
            float t0 = m[0]*w0  + m[1]*w1  + m[2]*w2  + m[3]*w3;
            float t1 = m[4]*w0  + m[5]*w1  + m[6]*w2  + m[7]*w3;
            float t2 = m[8]*w0  + m[9]*w1  + m[10]*w2 + m[11]*w3;
            float t3 = m[12]*w0 + m[13]*w1 + m[14]*w2 + m[15]*w3;
            w0 = t0; w1 = t1; w2 = t2; w3 = t3;
            float d   = w0*w0 + w1*w1 + w2*w2 + w3*w3;
            float inv = 1.0f / (sqrtf(d) + 1e-6f);
            gvR[n * BT + b] = make_float4(w0*inv, w1*inv, w2*inv, w3*inv);
        }
    }
    __syncthreads();   // global+shared visibility within block

    // ---------------- output phase: each thread 16 n's for its batch ----------------
    {
        const float s = sg[0];
        #pragma unroll 4
        for (int k = 0; k < 16; ++k) {
            const int n = r * 16 + k;
            float4 u = gvL[n * BT + b];     // coalesced 512B per warp, L2-hot
            float4 a = gvR[n * BT + b];
            float uu[4] = {u.x, u.y, u.z, u.w};
            float aa[4] = {a.x, a.y, a.z, a.w};

            float H0 = 0.f, H1 = 0.f, H2 = 0.f, H3 = 0.f;
            const float* bb = sB + n * 68;
            #pragma unroll
            for (int i = 0; i < 4; ++i) {
                #pragma unroll
                for (int l = 0; l < 4; ++l) {
                    float w = uu[i] * aa[l];
                    float4 bv = *(const float4*)(bb + i * 16 + l * 4);  // broadcast
                    H0 = fmaf(w, bv.x, H0);
                    H1 = fmaf(w, bv.y, H1);
                    H2 = fmaf(w, bv.z, H2);
                    H3 = fmaf(w, bv.w, H3);
                }
            }

            float f    = sqrtf(H0*H0 + H1*H1 + H2*H2 + H3*H3);
            float invf = s / (f + 1e-6f);
            H0 = fmaxf(nan0(H0 * invf), 0.f);
            H1 = fmaxf(nan0(H1 * invf), 0.f);
            H2 = fmaxf(nan0(H2 * invf), 0.f);
            H3 = fmaxf(nan0(H3 * invf), 0.f);

            float2 xn = sx[g * 65 + n];
            float y0 = fmaf(H0, xn.x, H1 * xn.y);
            float y1 = fmaf(H2, xn.x, H3 * xn.y);
            sx[g * 65 + n] = make_float2(y0, y1);
        }
    }
    __syncthreads();

    // ---------------- coalesced writeback ----------------
    float2* yv = (float2*)yg;
    for (int idx = tid; idx < G * NN; idx += TB)
        yv[(size_t)b0 * NN + idx] = sx[(idx >> 6) * 65 + (idx & 63)];
}

extern "C" void kernel_launch(void* const* d_in, const int* in_sizes, int n_in,
                              void* d_out, int out_size) {
    const float* x = (const float*)d_in[0];
    const float* A = (const float*)d_in[1];
    const float* B = (const float*)d_in[2];
    const float* s = (const float*)d_in[3];
    float* y = (float*)d_out;

    const int batch = in_sizes[0] / (NN * 2);   // 16384
    const int grid  = batch / G;                // 512

    tdvp_kernel<<<grid, TB>>>(x, A, B, s, y);
}

// round 6
// speedup vs baseline: 1.8948x; 1.1420x over previous
#include <cuda_runtime.h>
#include <cstddef>

#define NN 64
#define G  32          // batches per block
#define TB 128         // 4 role-warps per 32 batches
#define BT 16384       // total batches
#define KF 42          // fwd vector chain covers n = 1..KF
#define KB 21          // bwd vector chain covers n = KB..62; combine below

// global scratch (L2-temporal, coalesced [slot][b])
__device__ float4 gvL[NN * BT];              // normalized prefix vectors
__device__ float4 gvR[NN * BT];              // normalized suffix vectors
__device__ float4 gP[21 * 4 * BT];           // P(n)=M[KF..n-1], n=43..63, rows
__device__ float4 gQ[21 * 4 * BT];           // Q(n)=M[n+1..KB], n=0..20, rows

__device__ __forceinline__ float nan0(float h) {
    unsigned u = __float_as_uint(h);
    return ((u & 0x7fffffffu) > 0x7f800000u) ? 0.0f : h;
}

__global__ __launch_bounds__(TB, 4)
void tdvp_kernel(const float* __restrict__ xg, const float* __restrict__ Ag,
                 const float* __restrict__ Bg, const float* __restrict__ sg,
                 float* __restrict__ yg)
{
    __shared__ float  sA[NN * 32];       //  8 KB
    __shared__ float  sB[NN * 68];       // 17 KB padded
    __shared__ float2 sx[G * 65];        // 16.6 KB
    __shared__ float4 sBndL[G];          // raw q42 per batch
    __shared__ float4 sBndR[G];          // raw t21 per batch

    const int tid = threadIdx.x;
    const int b0  = blockIdx.x * G;

    for (int i = tid; i < NN * 32; i += TB) sA[i] = Ag[i];
    for (int i = tid; i < NN * 64; i += TB) sB[(i >> 6) * 68 + (i & 63)] = Bg[i];
    const float2* xv = (const float2*)xg;
    for (int idx = tid; idx < G * NN; idx += TB) {
        float2 v = xv[(size_t)b0 * NN + idx];
        float inv = rsqrtf(v.x * v.x + v.y * v.y);
        v.x *= inv; v.y *= inv;
        sx[(idx >> 6) * 65 + (idx & 63)] = v;
    }
    __syncthreads();

    const int g = tid & 31;
    const int r = tid >> 5;       // 0 fwd-vec, 1 fwd-mat, 2 bwd-vec, 3 bwd-mat
    const int b = b0 + g;

    // build M[nn] as 4 float4 rows (row l, cols r): M[l][r] = A[n,l,r,:].x
    #define BUILD_M4(nn, R0_, R1_, R2_, R3_)                                   \
    {                                                                          \
        float2 xn_ = sx[g * 65 + (nn)];                                        \
        const float4* ap_ = (const float4*)(sA + (nn) * 32);                   \
        float4 q0_ = ap_[0], q1_ = ap_[1], q2_ = ap_[2], q3_ = ap_[3];         \
        float4 q4_ = ap_[4], q5_ = ap_[5], q6_ = ap_[6], q7_ = ap_[7];         \
        R0_ = make_float4(fmaf(q0_.x, xn_.x, q0_.y * xn_.y),                   \
                          fmaf(q0_.z, xn_.x, q0_.w * xn_.y),                   \
                          fmaf(q1_.x, xn_.x, q1_.y * xn_.y),                   \
                          fmaf(q1_.z, xn_.x, q1_.w * xn_.y));                  \
        R1_ = make_float4(fmaf(q2_.x, xn_.x, q2_.y * xn_.y),                   \
                          fmaf(q2_.z, xn_.x, q2_.w * xn_.y),                   \
                          fmaf(q3_.x, xn_.x, q3_.y * xn_.y),                   \
                          fmaf(q3_.z, xn_.x, q3_.w * xn_.y));                  \
        R2_ = make_float4(fmaf(q4_.x, xn_.x, q4_.y * xn_.y),                   \
                          fmaf(q4_.z, xn_.x, q4_.w * xn_.y),                   \
                          fmaf(q5_.x, xn_.x, q5_.y * xn_.y),                   \
                          fmaf(q5_.z, xn_.x, q5_.w * xn_.y));                  \
        R3_ = make_float4(fmaf(q6_.x, xn_.x, q6_.y * xn_.y),                   \
                          fmaf(q6_.z, xn_.x, q6_.w * xn_.y),                   \
                          fmaf(q7_.x, xn_.x, q7_.y * xn_.y),                   \
                          fmaf(q7_.z, xn_.x, q7_.w * xn_.y));                  \
    }

    #define AXPY4(d, v_, M0, M1, M2, M3)                                       \
        d.x = fmaf(v_.x, M0.x, fmaf(v_.y, M1.x, fmaf(v_.z, M2.x, v_.w * M3.x)));\
        d.y = fmaf(v_.x, M0.y, fmaf(v_.y, M1.y, fmaf(v_.z, M2.y, v_.w * M3.y)));\
        d.z = fmaf(v_.x, M0.z, fmaf(v_.y, M1.z, fmaf(v_.z, M2.z, v_.w * M3.z)));\
        d.w = fmaf(v_.x, M0.w, fmaf(v_.y, M1.w, fmaf(v_.z, M2.w, v_.w * M3.w)));

    if (r == 0) {
        // fwd vector chain: v <- v * M[n-1], n = 1..KF; store normalized
        float4 v = make_float4(1.f, 0.f, 0.f, 0.f);
        #pragma unroll 2
        for (int n = 1; n <= KF; ++n) {
            float4 M0, M1, M2, M3;
            BUILD_M4(n - 1, M0, M1, M2, M3);
            float4 nv; AXPY4(nv, v, M0, M1, M2, M3);
            v = nv;
            float d = v.x*v.x + v.y*v.y + v.z*v.z + v.w*v.w;
            float inv = 1.0f / (sqrtf(d) + 1e-6f);
            gvL[n * BT + b] = make_float4(v.x*inv, v.y*inv, v.z*inv, v.w*inv);
        }
        sBndL[g] = v;                      // raw boundary q42
    } else if (r == 1) {
        // fwd matrix chain: P(n) = M[KF..n-1], n = 43..63; store rows
        float4 P0, P1, P2, P3;
        BUILD_M4(KF, P0, P1, P2, P3);
        gP[(0 * 4 + 0) * BT + b] = P0; gP[(0 * 4 + 1) * BT + b] = P1;
        gP[(0 * 4 + 2) * BT + b] = P2; gP[(0 * 4 + 3) * BT + b] = P3;
        #pragma unroll 2
        for (int n = KF + 2; n < NN; ++n) {
            float4 M0, M1, M2, M3;
            BUILD_M4(n - 1, M0, M1, M2, M3);
            float4 T0, T1, T2, T3;
            AXPY4(T0, P0, M0, M1, M2, M3);
            AXPY4(T1, P1, M0, M1, M2, M3);
            AXPY4(T2, P2, M0, M1, M2, M3);
            AXPY4(T3, P3, M0, M1, M2, M3);
            P0 = T0; P1 = T1; P2 = T2; P3 = T3;
            const int e = n - (KF + 1);
            gP[(e * 4 + 0) * BT + b] = P0; gP[(e * 4 + 1) * BT + b] = P1;
            gP[(e * 4 + 2) * BT + b] = P2; gP[(e * 4 + 3) * BT + b] = P3;
        }
    } else if (r == 2) {
        // bwd vector chain: w <- M[n+1] * w, n = 62..KB; store normalized
        float4 w = make_float4(1.f, 0.f, 0.f, 0.f);
        #pragma unroll 2
        for (int n = NN - 2; n >= KB; --n) {
            float4 M0, M1, M2, M3;
            BUILD_M4(n + 1, M0, M1, M2, M3);
            float4 nw;
            nw.x = fmaf(M0.x, w.x, fmaf(M0.y, w.y, fmaf(M0.z, w.z, M0.w * w.w)));
            nw.y = fmaf(M1.x, w.x, fmaf(M1.y, w.y, fmaf(M1.z, w.z, M1.w * w.w)));
            nw.z = fmaf(M2.x, w.x, fmaf(M2.y, w.y, fmaf(M2.z, w.z, M2.w * w.w)));
            nw.w = fmaf(M3.x, w.x, fmaf(M3.y, w.y, fmaf(M3.z, w.z, M3.w * w.w)));
            w = nw;
            float d = w.x*w.x + w.y*w.y + w.z*w.z + w.w*w.w;
            float inv = 1.0f / (sqrtf(d) + 1e-6f);
            gvR[n * BT + b] = make_float4(w.x*inv, w.y*inv, w.z*inv, w.w*inv);
        }
        sBndR[g] = w;                      // raw boundary t21 = raw vR(21)
    } else {
        // bwd matrix chain: Q(n) = M[n+1..KB], n = 20..0; store rows
        float4 Q0, Q1, Q2, Q3;
        BUILD_M4(KB, Q0, Q1, Q2, Q3);
        gQ[(20 * 4 + 0) * BT + b] = Q0; gQ[(20 * 4 + 1) * BT + b] = Q1;
        gQ[(20 * 4 + 2) * BT + b] = Q2; gQ[(20 * 4 + 3) * BT + b] = Q3;
        #pragma unroll 2
        for (int n = KB - 2; n >= 0; --n) {
            float4 M0, M1, M2, M3;
            BUILD_M4(n + 1, M0, M1, M2, M3);
            // Q <- M * Q : new row i = M[i][0]*Q0 + M[i][1]*Q1 + ...
            float4 T0, T1, T2, T3;
            AXPY4(T0, M0, Q0, Q1, Q2, Q3);
            AXPY4(T1, M1, Q0, Q1, Q2, Q3);
            AXPY4(T2, M2, Q0, Q1, Q2, Q3);
            AXPY4(T3, M3, Q0, Q1, Q2, Q3);
            Q0 = T0; Q1 = T1; Q2 = T2; Q3 = T3;
            gQ[(n * 4 + 0) * BT + b] = Q0; gQ[(n * 4 + 1) * BT + b] = Q1;
            gQ[(n * 4 + 2) * BT + b] = Q2; gQ[(n * 4 + 3) * BT + b] = Q3;
        }
    }
    __syncthreads();

    // ---------------- output phase: each thread 16 n's for its batch ----------------
    {
        const float s = sg[0];
        const float4 qb = sBndL[g];        // raw q42
        const float4 tb = sBndR[g];        // raw t21

        #pragma unroll 4
        for (int k = 0; k < 16; ++k) {
            const int n = r * 16 + k;

            float4 u;
            if (n == 0) u = make_float4(1.f, 0.f, 0.f, 0.f);
            else if (n <= KF) u = gvL[n * BT + b];
            else {
                const int e = n - (KF + 1);
                float4 R0 = gP[(e * 4 + 0) * BT + b];
                float4 R1 = gP[(e * 4 + 1) * BT + b];
                float4 R2 = gP[(e * 4 + 2) * BT + b];
                float4 R3 = gP[(e * 4 + 3) * BT + b];
                float4 raw; AXPY4(raw, qb, R0, R1, R2, R3);
                float d = raw.x*raw.x + raw.y*raw.y + raw.z*raw.z + raw.w*raw.w;
                float inv = 1.0f / (sqrtf(d) + 1e-6f);
                u = make_float4(raw.x*inv, raw.y*inv, raw.z*inv, raw.w*inv);
            }

            float4 a;
            if (n == NN - 1) a = make_float4(1.f, 0.f, 0.f, 0.f);
            else if (n >= KB) a = gvR[n * BT + b];
            else {
                float4 R0 = gQ[(n * 4 + 0) * BT + b];
                float4 R1 = gQ[(n * 4 + 1) * BT + b];
                float4 R2 = gQ[(n * 4 + 2) * BT + b];
                float4 R3 = gQ[(n * 4 + 3) * BT + b];
                float4 raw;
                raw.x = fmaf(R0.x, tb.x, fmaf(R0.y, tb.y, fmaf(R0.z, tb.z, R0.w * tb.w)));
                raw.y = fmaf(R1.x, tb.x, fmaf(R1.y, tb.y, fmaf(R1.z, tb.z, R1.w * tb.w)));
                raw.z = fmaf(R2.x, tb.x, fmaf(R2.y, tb.y, fmaf(R2.z, tb.z, R2.w * tb.w)));
                raw.w = fmaf(R3.x, tb.x, fmaf(R3.y, tb.y, fmaf(R3.z, tb.z, R3.w * tb.w)));
                float d = raw.x*raw.x + raw.y*raw.y + raw.z*raw.z + raw.w*raw.w;
                float inv = 1.0f / (sqrtf(d) + 1e-6f);
                a = make_float4(raw.x*inv, raw.y*inv, raw.z*inv, raw.w*inv);
            }

            float uu[4] = {u.x, u.y, u.z, u.w};
            float aa[4] = {a.x, a.y, a.z, a.w};
            float H0 = 0.f, H1 = 0.f, H2 = 0.f, H3 = 0.f;
            const float* bb = sB + n * 68;
            #pragma unroll
            for (int i = 0; i < 4; ++i) {
                #pragma unroll
                for (int l = 0; l < 4; ++l) {
                    float w = uu[i] * aa[l];
                    float4 bv = *(const float4*)(bb + i * 16 + l * 4);  // broadcast
                    H0 = fmaf(w, bv.x, H0);
                    H1 = fmaf(w, bv.y, H1);
                    H2 = fmaf(w, bv.z, H2);
                    H3 = fmaf(w, bv.w, H3);
                }
            }

            float f    = sqrtf(H0*H0 + H1*H1 + H2*H2 + H3*H3);
            float invf = s / (f + 1e-6f);
            H0 = fmaxf(nan0(H0 * invf), 0.f);
            H1 = fmaxf(nan0(H1 * invf), 0.f);
            H2 = fmaxf(nan0(H2 * invf), 0.f);
            H3 = fmaxf(nan0(H3 * invf), 0.f);

            float2 xn = sx[g * 65 + n];
            float y0 = fmaf(H0, xn.x, H1 * xn.y);
            float y1 = fmaf(H2, xn.x, H3 * xn.y);
            sx[g * 65 + n] = make_float2(y0, y1);
        }
    }
    __syncthreads();

    float2* yv = (float2*)yg;
    for (int idx = tid; idx < G * NN; idx += TB)
        yv[(size_t)b0 * NN + idx] = sx[(idx >> 6) * 65 + (idx & 63)];
}

extern "C" void kernel_launch(void* const* d_in, const int* in_sizes, int n_in,
                              void* d_out, int out_size) {
    const float* x = (const float*)d_in[0];
    const float* A = (const float*)d_in[1];
    const float* B = (const float*)d_in[2];
    const float* s = (const float*)d_in[3];
    float* y = (float*)d_out;

    const int batch = in_sizes[0] / (NN * 2);   // 16384
    const int grid  = batch / G;                // 512

    tdvp_kernel<<<grid, TB>>>(x, A, B, s, y);
}